// round 2
// baseline (speedup 1.0000x reference)
#include <cuda_runtime.h>
#include <math.h>

#define B_  2
#define S_  1024
#define P_  1024
#define D_  1024
#define H_  16
#define DH_ 64
#define T_  2048   // P + S
#define NT_ 2048   // B * S tokens
#define D3_ 3072
#define D4_ 4096

// ---------------- scratch (static device globals; no runtime alloc) ----------------
__device__ float g_h   [NT_ * D_];        // ln1 out
__device__ float g_qkv [NT_ * D3_];       // qkv
__device__ float g_Kall[B_*H_*DH_*T_];    // [b,h,d,t]
__device__ float g_Vall[B_*H_*T_*DH_];    // [b,h,t,d]
__device__ float g_a   [NT_ * D_];        // attn out (b,s,h*dh layout)
__device__ float g_x1  [NT_ * D_];        // x + proj
__device__ float g_h2  [NT_ * D_];        // ln2 out
__device__ float g_m   [NT_ * D4_];       // mlp hidden

// ---------------- layernorm ----------------
__global__ void ln_kernel(const float* __restrict__ X, const float* __restrict__ w,
                          const float* __restrict__ bia, float* __restrict__ Y) {
    __shared__ float red1[8];
    __shared__ float red2[8];
    int row = blockIdx.x;
    int tid = threadIdx.x;
    float4 v = ((const float4*)(X + (size_t)row * D_))[tid];
    float s = v.x + v.y + v.z + v.w;
    #pragma unroll
    for (int o = 16; o; o >>= 1) s += __shfl_xor_sync(0xffffffffu, s, o);
    if ((tid & 31) == 0) red1[tid >> 5] = s;
    __syncthreads();
    float u = 0.f;
    #pragma unroll
    for (int i = 0; i < 8; i++) u += red1[i];
    u *= (1.0f / D_);
    float dx = v.x - u, dy = v.y - u, dz = v.z - u, dw = v.w - u;
    float q = dx*dx + dy*dy + dz*dz + dw*dw;
    #pragma unroll
    for (int o = 16; o; o >>= 1) q += __shfl_xor_sync(0xffffffffu, q, o);
    if ((tid & 31) == 0) red2[tid >> 5] = q;
    __syncthreads();
    float var = 0.f;
    #pragma unroll
    for (int i = 0; i < 8; i++) var += red2[i];
    var *= (1.0f / D_);
    float inv = rsqrtf(var + 1e-12f);
    float4 wv = ((const float4*)w)[tid];
    float4 bv = ((const float4*)bia)[tid];
    float4 o;
    o.x = wv.x * (dx * inv) + bv.x;
    o.y = wv.y * (dy * inv) + bv.y;
    o.z = wv.z * (dz * inv) + bv.z;
    o.w = wv.w * (dw * inv) + bv.w;
    ((float4*)(Y + (size_t)row * D_))[tid] = o;
}

// ---------------- GEMM 128x128x8, 256 threads, 8x8/thread ----------------
__device__ __forceinline__ float gelu_f(float x) {
    float x3 = x * x * x;
    return 0.5f * x * (1.0f + tanhf(0.7978845608028654f * (x + 0.044715f * x3)));
}

template<int EPI>  // 0: +bias  1: gelu(+bias)  2: +bias+residual
__global__ __launch_bounds__(256, 2)
void sgemm_kernel(const float* __restrict__ A, const float* __restrict__ W,
                  const float* __restrict__ bias, const float* __restrict__ R,
                  float* __restrict__ C, int M, int N, int K) {
    __shared__ float As[8][132];
    __shared__ float Bs[8][128];
    int tid  = threadIdx.x;
    int row0 = blockIdx.y * 128, col0 = blockIdx.x * 128;
    int arow = tid >> 1, acol = (tid & 1) * 4;
    int brow = tid >> 5, bcol = (tid & 31) * 4;
    const float* Ap = A + (size_t)(row0 + arow) * K + acol;
    const float* Wp = W + (size_t)brow * N + col0 + bcol;
    int tx = tid & 15, ty = tid >> 4;
    float acc[8][8];
    #pragma unroll
    for (int i = 0; i < 8; i++)
        #pragma unroll
        for (int j = 0; j < 8; j++) acc[i][j] = 0.f;

    for (int k0 = 0; k0 < K; k0 += 8) {
        float4 av = *(const float4*)Ap;
        float4 bv = *(const float4*)Wp;
        As[acol + 0][arow] = av.x;
        As[acol + 1][arow] = av.y;
        As[acol + 2][arow] = av.z;
        As[acol + 3][arow] = av.w;
        *(float4*)&Bs[brow][bcol] = bv;
        __syncthreads();
        #pragma unroll
        for (int kk = 0; kk < 8; kk++) {
            float a[8], b[8];
            float4 t0 = *(const float4*)&As[kk][ty * 4];
            float4 t1 = *(const float4*)&As[kk][64 + ty * 4];
            a[0]=t0.x; a[1]=t0.y; a[2]=t0.z; a[3]=t0.w;
            a[4]=t1.x; a[5]=t1.y; a[6]=t1.z; a[7]=t1.w;
            float4 u0 = *(const float4*)&Bs[kk][tx * 4];
            float4 u1 = *(const float4*)&Bs[kk][64 + tx * 4];
            b[0]=u0.x; b[1]=u0.y; b[2]=u0.z; b[3]=u0.w;
            b[4]=u1.x; b[5]=u1.y; b[6]=u1.z; b[7]=u1.w;
            #pragma unroll
            for (int i = 0; i < 8; i++)
                #pragma unroll
                for (int j = 0; j < 8; j++)
                    acc[i][j] += a[i] * b[j];
        }
        __syncthreads();
        Ap += 8;
        Wp += (size_t)8 * N;
    }

    #pragma unroll
    for (int i = 0; i < 8; i++) {
        int r = row0 + ((i < 4) ? ty * 4 + i : 64 + ty * 4 + (i - 4));
        #pragma unroll
        for (int j = 0; j < 8; j++) {
            int c = col0 + ((j < 4) ? tx * 4 + j : 64 + tx * 4 + (j - 4));
            float v = acc[i][j] + bias[c];
            if (EPI == 1) v = gelu_f(v);
            if (EPI == 2) v += R[(size_t)r * N + c];
            C[(size_t)r * N + c] = v;
        }
    }
}

// ---------------- KV assembly ----------------
__global__ void copy_past_k(const float* __restrict__ kin) {
    int idx = blockIdx.x * blockDim.x + threadIdx.x;   // float4 index, 524288 total
    int e = idx * 4;
    int bhd = e >> 10;          // (b*H+h)*DH + d
    int t   = e & 1023;
    *(float4*)&g_Kall[(size_t)bhd * T_ + t] = *(const float4*)&kin[e];
}

__global__ void copy_past_v(const float* __restrict__ vin) {
    int idx = blockIdx.x * blockDim.x + threadIdx.x;   // float4 index, 524288 total
    int e = idx * 4;
    int bh  = e >> 16;          // P*DH = 65536 per (b,h)
    int rem = e & 65535;
    *(float4*)&g_Vall[(size_t)bh * T_ * DH_ + rem] = *(const float4*)&vin[e];
}

__global__ void scatter_kv(const float* __restrict__ qkv,
                           float* __restrict__ outk, float* __restrict__ outv) {
    int idx = blockIdx.x * blockDim.x + threadIdx.x;   // over NT_*D_ = 2M
    int bs = idx >> 10;          // token index
    int hd = idx & 1023;
    int b = bs >> 10, s = bs & 1023;
    int h = hd >> 6,  d = hd & 63;
    float kkv = qkv[(size_t)bs * D3_ + D_     + hd];
    float vvv = qkv[(size_t)bs * D3_ + 2 * D_ + hd];
    size_t kpos = (size_t)(b * H_ + h) * DH_ + d;
    g_Kall[kpos * T_ + P_ + s] = kkv;
    outk[kpos * S_ + s] = kkv;
    size_t vrow = (size_t)(b * H_ + h) * T_ + P_ + s;
    g_Vall[vrow * DH_ + d] = vvv;
    outv[((size_t)(b * H_ + h) * S_ + s) * DH_ + d] = vvv;
}

// ---------------- flash attention (fp32, Br=Bc=64) ----------------
__global__ __launch_bounds__(256)
void attn_kernel(const float* __restrict__ qkv, float* __restrict__ Ab) {
    extern __shared__ float sm[];
    float (*Qs)[68] = (float(*)[68])(sm);
    float (*Ks)[68] = (float(*)[68])(sm + 64 * 68);       // Ks[d][j]
    float (*Vs)[68] = (float(*)[68])(sm + 2 * 64 * 68);   // Vs[j][d]
    float (*Ps)[68] = (float(*)[68])(sm + 3 * 64 * 68);
    int bh = blockIdx.x, b = bh >> 4;
    int h = bh & 15;
    int s0 = blockIdx.y * 64;
    int tid = threadIdx.x, tc = tid & 15, tr = tid >> 4;

    for (int it = tid; it < 1024; it += 256) {
        int r = it >> 4, c4 = (it & 15) << 2;
        *(float4*)&Qs[r][c4] =
            *(const float4*)&qkv[(size_t)(b * S_ + s0 + r) * D3_ + h * DH_ + c4];
    }
    const float* Kb = g_Kall + (size_t)bh * DH_ * T_;
    const float* Vb = g_Vall + (size_t)bh * T_ * DH_;

    float m0[4], l0[4], O[4][4];
    #pragma unroll
    for (int i = 0; i < 4; i++) {
        m0[i] = -INFINITY; l0[i] = 0.f;
        #pragma unroll
        for (int j = 0; j < 4; j++) O[i][j] = 0.f;
    }

    for (int t0 = 0; t0 < T_; t0 += 64) {
        __syncthreads();
        for (int it = tid; it < 1024; it += 256) {
            int r = it >> 4, c4 = (it & 15) << 2;
            *(float4*)&Ks[r][c4] = *(const float4*)&Kb[(size_t)r * T_ + t0 + c4];
            *(float4*)&Vs[r][c4] = *(const float4*)&Vb[(size_t)(t0 + r) * DH_ + c4];
        }
        __syncthreads();

        float sv[4][4];
        #pragma unroll
        for (int i = 0; i < 4; i++)
            #pragma unroll
            for (int j = 0; j < 4; j++) sv[i][j] = 0.f;

        #pragma unroll 4
        for (int d = 0; d < 64; d++) {
            float4 kf = *(const float4*)&Ks[d][tc << 2];
            #pragma unroll
            for (int ii = 0; ii < 4; ii++) {
                float q = Qs[tr * 4 + ii][d];
                sv[ii][0] += q * kf.x;
                sv[ii][1] += q * kf.y;
                sv[ii][2] += q * kf.z;
                sv[ii][3] += q * kf.w;
            }
        }

        #pragma unroll
        for (int ii = 0; ii < 4; ii++) {
            float mx = fmaxf(fmaxf(sv[ii][0], sv[ii][1]), fmaxf(sv[ii][2], sv[ii][3]));
            #pragma unroll
            for (int o = 8; o; o >>= 1) mx = fmaxf(mx, __shfl_xor_sync(0xffffffffu, mx, o));
            float mn = fmaxf(m0[ii], mx);
            float sc = __expf(m0[ii] - mn);
            float4 p;
            p.x = __expf(sv[ii][0] - mn);
            p.y = __expf(sv[ii][1] - mn);
            p.z = __expf(sv[ii][2] - mn);
            p.w = __expf(sv[ii][3] - mn);
            float ps = p.x + p.y + p.z + p.w;
            #pragma unroll
            for (int o = 8; o; o >>= 1) ps += __shfl_xor_sync(0xffffffffu, ps, o);
            l0[ii] = l0[ii] * sc + ps;
            m0[ii] = mn;
            O[ii][0] *= sc; O[ii][1] *= sc; O[ii][2] *= sc; O[ii][3] *= sc;
            *(float4*)&Ps[tr * 4 + ii][tc << 2] = p;
        }
        __syncthreads();

        #pragma unroll 4
        for (int j = 0; j < 64; j++) {
            float4 vf = *(const float4*)&Vs[j][tc << 2];
            #pragma unroll
            for (int ii = 0; ii < 4; ii++) {
                float p = Ps[tr * 4 + ii][j];
                O[ii][0] += p * vf.x;
                O[ii][1] += p * vf.y;
                O[ii][2] += p * vf.z;
                O[ii][3] += p * vf.w;
            }
        }
    }

    #pragma unroll
    for (int ii = 0; ii < 4; ii++) {
        float inv = 1.0f / l0[ii];
        float4 o;
        o.x = O[ii][0] * inv; o.y = O[ii][1] * inv;
        o.z = O[ii][2] * inv; o.w = O[ii][3] * inv;
        *(float4*)&Ab[(size_t)(b * S_ + s0 + tr * 4 + ii) * D_ + h * DH_ + (tc << 2)] = o;
    }
}

// ---------------- launch ----------------
extern "C" void kernel_launch(void* const* d_in, const int* in_sizes, int n_in,
                              void* d_out, int out_size) {
    const float* x      = (const float*)d_in[0];
    const float* kin    = (const float*)d_in[1];
    const float* vin    = (const float*)d_in[2];
    const float* ln1w   = (const float*)d_in[3];
    const float* ln1b   = (const float*)d_in[4];
    const float* ln2w   = (const float*)d_in[5];
    const float* ln2b   = (const float*)d_in[6];
    const float* w_attn = (const float*)d_in[7];
    const float* b_attn = (const float*)d_in[8];
    const float* w_proj = (const float*)d_in[9];
    const float* b_proj = (const float*)d_in[10];
    const float* w_fc   = (const float*)d_in[11];
    const float* b_fc   = (const float*)d_in[12];
    const float* w_fc2  = (const float*)d_in[13];
    const float* b_fc2  = (const float*)d_in[14];

    float* out_x = (float*)d_out;
    float* out_k = out_x + (size_t)NT_ * D_;
    float* out_v = out_k + (size_t)NT_ * D_;

    float *ph, *pqkv, *pa, *px1, *ph2, *pm;
    cudaGetSymbolAddress((void**)&ph,   g_h);
    cudaGetSymbolAddress((void**)&pqkv, g_qkv);
    cudaGetSymbolAddress((void**)&pa,   g_a);
    cudaGetSymbolAddress((void**)&px1,  g_x1);
    cudaGetSymbolAddress((void**)&ph2,  g_h2);
    cudaGetSymbolAddress((void**)&pm,   g_m);

    // 1. ln1
    ln_kernel<<<NT_, 256>>>(x, ln1w, ln1b, ph);
    // 2. qkv gemm
    sgemm_kernel<0><<<dim3(D3_ / 128, NT_ / 128), 256>>>(ph, w_attn, b_attn, nullptr,
                                                         pqkv, NT_, D3_, D_);
    // 3. assemble KV cache (+ write new_k/new_v outputs)
    copy_past_k<<<2048, 256>>>(kin);
    copy_past_v<<<2048, 256>>>(vin);
    scatter_kv<<<8192, 256>>>(pqkv, out_k, out_v);
    // 4. attention
    int attn_smem = 4 * 64 * 68 * (int)sizeof(float);  // 69632
    cudaFuncSetAttribute(attn_kernel, cudaFuncAttributeMaxDynamicSharedMemorySize, attn_smem);
    attn_kernel<<<dim3(B_ * H_, S_ / 64), 256, attn_smem>>>(pqkv, pa);
    // 5. proj + residual
    sgemm_kernel<2><<<dim3(D_ / 128, NT_ / 128), 256>>>(pa, w_proj, b_proj, x,
                                                        px1, NT_, D_, D_);
    // 6. ln2
    ln_kernel<<<NT_, 256>>>(px1, ln2w, ln2b, ph2);
    // 7. fc + gelu
    sgemm_kernel<1><<<dim3(D4_ / 128, NT_ / 128), 256>>>(ph2, w_fc, b_fc, nullptr,
                                                         pm, NT_, D4_, D_);
    // 8. fc2 + residual -> out x
    sgemm_kernel<2><<<dim3(D_ / 128, NT_ / 128), 256>>>(pm, w_fc2, b_fc2, px1,
                                                        out_x, NT_, D_, D4_);
}

// round 3
// speedup vs baseline: 2.0199x; 2.0199x over previous
#include <cuda_runtime.h>
#include <math.h>
#include <stdint.h>

#define B_  2
#define S_  1024
#define P_  1024
#define D_  1024
#define H_  16
#define DH_ 64
#define T_  2048   // P + S
#define NT_ 2048   // B * S tokens
#define D3_ 3072
#define D4_ 4096

// ---------------- scratch ----------------
__device__ float g_h   [NT_ * D_];
__device__ float g_qkv [NT_ * D3_];
__device__ float g_Kall[B_*H_*DH_*T_];    // [b,h,d,t]
__device__ float g_Vall[B_*H_*T_*DH_];    // [b,h,t,d]
__device__ float g_a   [NT_ * D_];
__device__ float g_x1  [NT_ * D_];
__device__ float g_h2  [NT_ * D_];
__device__ float g_m   [NT_ * D4_];

// ---------------- helpers ----------------
__device__ __forceinline__ uint32_t smem_u32(const void* p) {
    return (uint32_t)__cvta_generic_to_shared(p);
}
__device__ __forceinline__ void cp_async16(uint32_t saddr, const void* g) {
    asm volatile("cp.async.cg.shared.global [%0], [%1], 16;\n" :: "r"(saddr), "l"(g));
}
__device__ __forceinline__ void cp_commit() {
    asm volatile("cp.async.commit_group;\n");
}
template<int N>
__device__ __forceinline__ void cp_wait() {
    asm volatile("cp.async.wait_group %0;\n" :: "n"(N));
}
__device__ __forceinline__ uint32_t f2tf(float v) {
    uint32_t r;
    asm("cvt.rna.tf32.f32 %0, %1;" : "=r"(r) : "f"(v));
    return r;
}
__device__ __forceinline__ void mma_tf32(float* d, const uint32_t* a, const uint32_t* b) {
    asm volatile(
        "mma.sync.aligned.m16n8k8.row.col.f32.tf32.tf32.f32 "
        "{%0,%1,%2,%3}, {%4,%5,%6,%7}, {%8,%9}, {%0,%1,%2,%3};"
        : "+f"(d[0]), "+f"(d[1]), "+f"(d[2]), "+f"(d[3])
        : "r"(a[0]), "r"(a[1]), "r"(a[2]), "r"(a[3]), "r"(b[0]), "r"(b[1]));
}
__device__ __forceinline__ float gelu_f(float x) {
    float x3 = x * x * x;
    return 0.5f * x * (1.0f + tanhf(0.7978845608028654f * (x + 0.044715f * x3)));
}

// ---------------- layernorm ----------------
__global__ void ln_kernel(const float* __restrict__ X, const float* __restrict__ w,
                          const float* __restrict__ bia, float* __restrict__ Y) {
    __shared__ float red1[8];
    __shared__ float red2[8];
    int row = blockIdx.x;
    int tid = threadIdx.x;
    float4 v = ((const float4*)(X + (size_t)row * D_))[tid];
    float s = v.x + v.y + v.z + v.w;
    #pragma unroll
    for (int o = 16; o; o >>= 1) s += __shfl_xor_sync(0xffffffffu, s, o);
    if ((tid & 31) == 0) red1[tid >> 5] = s;
    __syncthreads();
    float u = 0.f;
    #pragma unroll
    for (int i = 0; i < 8; i++) u += red1[i];
    u *= (1.0f / D_);
    float dx = v.x - u, dy = v.y - u, dz = v.z - u, dw = v.w - u;
    float q = dx*dx + dy*dy + dz*dz + dw*dw;
    #pragma unroll
    for (int o = 16; o; o >>= 1) q += __shfl_xor_sync(0xffffffffu, q, o);
    if ((tid & 31) == 0) red2[tid >> 5] = q;
    __syncthreads();
    float var = 0.f;
    #pragma unroll
    for (int i = 0; i < 8; i++) var += red2[i];
    var *= (1.0f / D_);
    float inv = rsqrtf(var + 1e-12f);
    float4 wv = ((const float4*)w)[tid];
    float4 bv = ((const float4*)bia)[tid];
    float4 o;
    o.x = wv.x * (dx * inv) + bv.x;
    o.y = wv.y * (dy * inv) + bv.y;
    o.z = wv.z * (dz * inv) + bv.z;
    o.w = wv.w * (dw * inv) + bv.w;
    ((float4*)(Y + (size_t)row * D_))[tid] = o;
}

// ---------------- tf32 tensor-core GEMM: 128x128x16 tile, 8 warps ----------------
// EPI: 0 = +bias, 1 = gelu(+bias), 2 = +bias+residual
template<int EPI>
__global__ __launch_bounds__(256)
void tgemm_kernel(const float* __restrict__ A, const float* __restrict__ W,
                  const float* __restrict__ bias, const float* __restrict__ R,
                  float* __restrict__ C, int M, int N, int K) {
    __shared__ float As[2][128][20];   // [stage][m][k], pad 4 -> conflict-free frag loads
    __shared__ float Bs[2][16][136];   // [stage][k][n], pad 8 -> conflict-free frag loads

    int tid = threadIdx.x, lane = tid & 31, wid = tid >> 5;
    int wm = wid >> 1, wn = wid & 1;            // warp grid 4x2; warp tile 32x64
    int row0 = blockIdx.y * 128, col0 = blockIdx.x * 128;
    int g = lane >> 2, tq = lane & 3;

    float acc[2][8][4];
    #pragma unroll
    for (int mi = 0; mi < 2; mi++)
        #pragma unroll
        for (int ni = 0; ni < 8; ni++)
            #pragma unroll
            for (int r = 0; r < 4; r++) acc[mi][ni][r] = 0.f;

    auto prefetch = [&](int st, int k0) {
        #pragma unroll
        for (int i = 0; i < 2; i++) {
            int c = tid + 256 * i;
            int ar = c >> 2, ac = (c & 3) << 2;
            cp_async16(smem_u32(&As[st][ar][ac]),
                       A + (size_t)(row0 + ar) * K + k0 + ac);
            int br = c >> 5, bc = (c & 31) << 2;
            cp_async16(smem_u32(&Bs[st][br][bc]),
                       W + (size_t)(k0 + br) * N + col0 + bc);
        }
        cp_commit();
    };

    int NK = K >> 4;
    prefetch(0, 0);
    for (int kt = 0; kt < NK; kt++) {
        int st = kt & 1;
        if (kt + 1 < NK) {
            prefetch(st ^ 1, (kt + 1) << 4);
            cp_wait<1>();
        } else {
            cp_wait<0>();
        }
        __syncthreads();

        #pragma unroll
        for (int kk = 0; kk < 16; kk += 8) {
            uint32_t af[2][4], bf[8][2];
            #pragma unroll
            for (int mi = 0; mi < 2; mi++) {
                int mb = wm * 32 + mi * 16;
                af[mi][0] = f2tf(As[st][mb + g][kk + tq]);
                af[mi][1] = f2tf(As[st][mb + g + 8][kk + tq]);
                af[mi][2] = f2tf(As[st][mb + g][kk + tq + 4]);
                af[mi][3] = f2tf(As[st][mb + g + 8][kk + tq + 4]);
            }
            #pragma unroll
            for (int ni = 0; ni < 8; ni++) {
                int nb = wn * 64 + ni * 8;
                bf[ni][0] = f2tf(Bs[st][kk + tq][nb + g]);
                bf[ni][1] = f2tf(Bs[st][kk + tq + 4][nb + g]);
            }
            #pragma unroll
            for (int mi = 0; mi < 2; mi++)
                #pragma unroll
                for (int ni = 0; ni < 8; ni++)
                    mma_tf32(acc[mi][ni], af[mi], bf[ni]);
        }
        __syncthreads();
    }

    // epilogue
    #pragma unroll
    for (int mi = 0; mi < 2; mi++) {
        int rA = row0 + wm * 32 + mi * 16 + g;       // rows for c0,c1
        int rB = rA + 8;                             // rows for c2,c3
        #pragma unroll
        for (int ni = 0; ni < 8; ni++) {
            int cg = col0 + wn * 64 + ni * 8 + 2 * tq;
            float b0 = bias[cg], b1 = bias[cg + 1];
            float v0 = acc[mi][ni][0] + b0;
            float v1 = acc[mi][ni][1] + b1;
            float v2 = acc[mi][ni][2] + b0;
            float v3 = acc[mi][ni][3] + b1;
            if (EPI == 1) {
                v0 = gelu_f(v0); v1 = gelu_f(v1);
                v2 = gelu_f(v2); v3 = gelu_f(v3);
            }
            if (EPI == 2) {
                v0 += R[(size_t)rA * N + cg];
                v1 += R[(size_t)rA * N + cg + 1];
                v2 += R[(size_t)rB * N + cg];
                v3 += R[(size_t)rB * N + cg + 1];
            }
            *(float2*)&C[(size_t)rA * N + cg] = make_float2(v0, v1);
            *(float2*)&C[(size_t)rB * N + cg] = make_float2(v2, v3);
        }
    }
}

// ---------------- KV assembly ----------------
__global__ void copy_past_k(const float* __restrict__ kin) {
    int idx = blockIdx.x * blockDim.x + threadIdx.x;
    int e = idx * 4;
    int bhd = e >> 10;
    int t   = e & 1023;
    *(float4*)&g_Kall[(size_t)bhd * T_ + t] = *(const float4*)&kin[e];
}

__global__ void copy_past_v(const float* __restrict__ vin) {
    int idx = blockIdx.x * blockDim.x + threadIdx.x;
    int e = idx * 4;
    int bh  = e >> 16;
    int rem = e & 65535;
    *(float4*)&g_Vall[(size_t)bh * T_ * DH_ + rem] = *(const float4*)&vin[e];
}

__global__ void scatter_kv(const float* __restrict__ qkv,
                           float* __restrict__ outk, float* __restrict__ outv) {
    int idx = blockIdx.x * blockDim.x + threadIdx.x;
    int bs = idx >> 10;
    int hd = idx & 1023;
    int b = bs >> 10, s = bs & 1023;
    int h = hd >> 6,  d = hd & 63;
    float kkv = qkv[(size_t)bs * D3_ + D_     + hd];
    float vvv = qkv[(size_t)bs * D3_ + 2 * D_ + hd];
    size_t kpos = (size_t)(b * H_ + h) * DH_ + d;
    g_Kall[kpos * T_ + P_ + s] = kkv;
    outk[kpos * S_ + s] = kkv;
    size_t vrow = (size_t)(b * H_ + h) * T_ + P_ + s;
    g_Vall[vrow * DH_ + d] = vvv;
    outv[((size_t)(b * H_ + h) * S_ + s) * DH_ + d] = vvv;
}

// ---------------- flash attention (fp32, Br=Bc=64) ----------------
__global__ __launch_bounds__(256)
void attn_kernel(const float* __restrict__ qkv, float* __restrict__ Ab) {
    extern __shared__ float sm[];
    float (*Qs)[68] = (float(*)[68])(sm);
    float (*Ks)[68] = (float(*)[68])(sm + 64 * 68);
    float (*Vs)[68] = (float(*)[68])(sm + 2 * 64 * 68);
    float (*Ps)[68] = (float(*)[68])(sm + 3 * 64 * 68);
    int bh = blockIdx.x, b = bh >> 4;
    int h = bh & 15;
    int s0 = blockIdx.y * 64;
    int tid = threadIdx.x, tc = tid & 15, tr = tid >> 4;

    for (int it = tid; it < 1024; it += 256) {
        int r = it >> 4, c4 = (it & 15) << 2;
        *(float4*)&Qs[r][c4] =
            *(const float4*)&qkv[(size_t)(b * S_ + s0 + r) * D3_ + h * DH_ + c4];
    }
    const float* Kb = g_Kall + (size_t)bh * DH_ * T_;
    const float* Vb = g_Vall + (size_t)bh * T_ * DH_;

    float m0[4], l0[4], O[4][4];
    #pragma unroll
    for (int i = 0; i < 4; i++) {
        m0[i] = -INFINITY; l0[i] = 0.f;
        #pragma unroll
        for (int j = 0; j < 4; j++) O[i][j] = 0.f;
    }

    for (int t0 = 0; t0 < T_; t0 += 64) {
        __syncthreads();
        for (int it = tid; it < 1024; it += 256) {
            int r = it >> 4, c4 = (it & 15) << 2;
            *(float4*)&Ks[r][c4] = *(const float4*)&Kb[(size_t)r * T_ + t0 + c4];
            *(float4*)&Vs[r][c4] = *(const float4*)&Vb[(size_t)(t0 + r) * DH_ + c4];
        }
        __syncthreads();

        float sv[4][4];
        #pragma unroll
        for (int i = 0; i < 4; i++)
            #pragma unroll
            for (int j = 0; j < 4; j++) sv[i][j] = 0.f;

        #pragma unroll 4
        for (int d = 0; d < 64; d++) {
            float4 kf = *(const float4*)&Ks[d][tc << 2];
            #pragma unroll
            for (int ii = 0; ii < 4; ii++) {
                float q = Qs[tr * 4 + ii][d];
                sv[ii][0] += q * kf.x;
                sv[ii][1] += q * kf.y;
                sv[ii][2] += q * kf.z;
                sv[ii][3] += q * kf.w;
            }
        }

        #pragma unroll
        for (int ii = 0; ii < 4; ii++) {
            float mx = fmaxf(fmaxf(sv[ii][0], sv[ii][1]), fmaxf(sv[ii][2], sv[ii][3]));
            #pragma unroll
            for (int o = 8; o; o >>= 1) mx = fmaxf(mx, __shfl_xor_sync(0xffffffffu, mx, o));
            float mn = fmaxf(m0[ii], mx);
            float sc = __expf(m0[ii] - mn);
            float4 p;
            p.x = __expf(sv[ii][0] - mn);
            p.y = __expf(sv[ii][1] - mn);
            p.z = __expf(sv[ii][2] - mn);
            p.w = __expf(sv[ii][3] - mn);
            float ps = p.x + p.y + p.z + p.w;
            #pragma unroll
            for (int o = 8; o; o >>= 1) ps += __shfl_xor_sync(0xffffffffu, ps, o);
            l0[ii] = l0[ii] * sc + ps;
            m0[ii] = mn;
            O[ii][0] *= sc; O[ii][1] *= sc; O[ii][2] *= sc; O[ii][3] *= sc;
            *(float4*)&Ps[tr * 4 + ii][tc << 2] = p;
        }
        __syncthreads();

        #pragma unroll 4
        for (int j = 0; j < 64; j++) {
            float4 vf = *(const float4*)&Vs[j][tc << 2];
            #pragma unroll
            for (int ii = 0; ii < 4; ii++) {
                float p = Ps[tr * 4 + ii][j];
                O[ii][0] += p * vf.x;
                O[ii][1] += p * vf.y;
                O[ii][2] += p * vf.z;
                O[ii][3] += p * vf.w;
            }
        }
    }

    #pragma unroll
    for (int ii = 0; ii < 4; ii++) {
        float inv = 1.0f / l0[ii];
        float4 o;
        o.x = O[ii][0] * inv; o.y = O[ii][1] * inv;
        o.z = O[ii][2] * inv; o.w = O[ii][3] * inv;
        *(float4*)&Ab[(size_t)(b * S_ + s0 + tr * 4 + ii) * D_ + h * DH_ + (tc << 2)] = o;
    }
}

// ---------------- launch ----------------
extern "C" void kernel_launch(void* const* d_in, const int* in_sizes, int n_in,
                              void* d_out, int out_size) {
    const float* x      = (const float*)d_in[0];
    const float* kin    = (const float*)d_in[1];
    const float* vin    = (const float*)d_in[2];
    const float* ln1w   = (const float*)d_in[3];
    const float* ln1b   = (const float*)d_in[4];
    const float* ln2w   = (const float*)d_in[5];
    const float* ln2b   = (const float*)d_in[6];
    const float* w_attn = (const float*)d_in[7];
    const float* b_attn = (const float*)d_in[8];
    const float* w_proj = (const float*)d_in[9];
    const float* b_proj = (const float*)d_in[10];
    const float* w_fc   = (const float*)d_in[11];
    const float* b_fc   = (const float*)d_in[12];
    const float* w_fc2  = (const float*)d_in[13];
    const float* b_fc2  = (const float*)d_in[14];

    float* out_x = (float*)d_out;
    float* out_k = out_x + (size_t)NT_ * D_;
    float* out_v = out_k + (size_t)NT_ * D_;

    float *ph, *pqkv, *pa, *px1, *ph2, *pm;
    cudaGetSymbolAddress((void**)&ph,   g_h);
    cudaGetSymbolAddress((void**)&pqkv, g_qkv);
    cudaGetSymbolAddress((void**)&pa,   g_a);
    cudaGetSymbolAddress((void**)&px1,  g_x1);
    cudaGetSymbolAddress((void**)&ph2,  g_h2);
    cudaGetSymbolAddress((void**)&pm,   g_m);

    // 1. ln1
    ln_kernel<<<NT_, 256>>>(x, ln1w, ln1b, ph);
    // 2. qkv gemm (tf32 MMA)
    tgemm_kernel<0><<<dim3(D3_ / 128, NT_ / 128), 256>>>(ph, w_attn, b_attn, nullptr,
                                                         pqkv, NT_, D3_, D_);
    // 3. assemble KV cache (+ write new_k/new_v outputs)
    copy_past_k<<<2048, 256>>>(kin);
    copy_past_v<<<2048, 256>>>(vin);
    scatter_kv<<<8192, 256>>>(pqkv, out_k, out_v);
    // 4. attention
    int attn_smem = 4 * 64 * 68 * (int)sizeof(float);  // 69632
    cudaFuncSetAttribute(attn_kernel, cudaFuncAttributeMaxDynamicSharedMemorySize, attn_smem);
    attn_kernel<<<dim3(B_ * H_, S_ / 64), 256, attn_smem>>>(pqkv, pa);
    // 5. proj + residual
    tgemm_kernel<2><<<dim3(D_ / 128, NT_ / 128), 256>>>(pa, w_proj, b_proj, x,
                                                        px1, NT_, D_, D_);
    // 6. ln2
    ln_kernel<<<NT_, 256>>>(px1, ln2w, ln2b, ph2);
    // 7. fc + gelu
    tgemm_kernel<1><<<dim3(D4_ / 128, NT_ / 128), 256>>>(ph2, w_fc, b_fc, nullptr,
                                                         pm, NT_, D4_, D_);
    // 8. fc2 + residual -> out x
    tgemm_kernel<2><<<dim3(D_ / 128, NT_ / 128), 256>>>(pm, w_fc2, b_fc2, px1,
                                                        out_x, NT_, D_, D4_);
}

// round 4
// speedup vs baseline: 2.9615x; 1.4662x over previous
#include <cuda_runtime.h>
#include <math.h>
#include <stdint.h>

#define B_  2
#define S_  1024
#define P_  1024
#define D_  1024
#define H_  16
#define DH_ 64
#define T_  2048   // P + S
#define NT_ 2048   // B * S tokens
#define D3_ 3072
#define D4_ 4096

// ---------------- scratch ----------------
__device__ float g_h   [NT_ * D_];
__device__ float g_qkv [NT_ * D3_];
__device__ float g_Kall[B_*H_*DH_*T_];    // [b,h,d,t]
__device__ float g_Vall[B_*H_*T_*DH_];    // [b,h,t,d]
__device__ float g_a   [NT_ * D_];
__device__ float g_x1  [NT_ * D_];
__device__ float g_h2  [NT_ * D_];
__device__ float g_m   [NT_ * D4_];

// ---------------- helpers ----------------
__device__ __forceinline__ uint32_t smem_u32(const void* p) {
    return (uint32_t)__cvta_generic_to_shared(p);
}
__device__ __forceinline__ void cp_async16(uint32_t saddr, const void* g) {
    asm volatile("cp.async.cg.shared.global [%0], [%1], 16;\n" :: "r"(saddr), "l"(g));
}
__device__ __forceinline__ void cp_commit() {
    asm volatile("cp.async.commit_group;\n");
}
template<int N>
__device__ __forceinline__ void cp_wait() {
    asm volatile("cp.async.wait_group %0;\n" :: "n"(N));
}
__device__ __forceinline__ uint32_t f2tf(float v) {
    uint32_t r;
    asm("cvt.rna.tf32.f32 %0, %1;" : "=r"(r) : "f"(v));
    return r;
}
__device__ __forceinline__ void mma_tf32(float* d, const uint32_t* a, const uint32_t* b) {
    asm volatile(
        "mma.sync.aligned.m16n8k8.row.col.f32.tf32.tf32.f32 "
        "{%0,%1,%2,%3}, {%4,%5,%6,%7}, {%8,%9}, {%0,%1,%2,%3};"
        : "+f"(d[0]), "+f"(d[1]), "+f"(d[2]), "+f"(d[3])
        : "r"(a[0]), "r"(a[1]), "r"(a[2]), "r"(a[3]), "r"(b[0]), "r"(b[1]));
}
__device__ __forceinline__ float gelu_f(float x) {
    float x3 = x * x * x;
    return 0.5f * x * (1.0f + tanhf(0.7978845608028654f * (x + 0.044715f * x3)));
}

// ---------------- layernorm ----------------
__global__ void ln_kernel(const float* __restrict__ X, const float* __restrict__ w,
                          const float* __restrict__ bia, float* __restrict__ Y) {
    __shared__ float red1[8];
    __shared__ float red2[8];
    int row = blockIdx.x;
    int tid = threadIdx.x;
    float4 v = ((const float4*)(X + (size_t)row * D_))[tid];
    float s = v.x + v.y + v.z + v.w;
    #pragma unroll
    for (int o = 16; o; o >>= 1) s += __shfl_xor_sync(0xffffffffu, s, o);
    if ((tid & 31) == 0) red1[tid >> 5] = s;
    __syncthreads();
    float u = 0.f;
    #pragma unroll
    for (int i = 0; i < 8; i++) u += red1[i];
    u *= (1.0f / D_);
    float dx = v.x - u, dy = v.y - u, dz = v.z - u, dw = v.w - u;
    float q = dx*dx + dy*dy + dz*dz + dw*dw;
    #pragma unroll
    for (int o = 16; o; o >>= 1) q += __shfl_xor_sync(0xffffffffu, q, o);
    if ((tid & 31) == 0) red2[tid >> 5] = q;
    __syncthreads();
    float var = 0.f;
    #pragma unroll
    for (int i = 0; i < 8; i++) var += red2[i];
    var *= (1.0f / D_);
    float inv = rsqrtf(var + 1e-12f);
    float4 wv = ((const float4*)w)[tid];
    float4 bv = ((const float4*)bia)[tid];
    float4 o;
    o.x = wv.x * (dx * inv) + bv.x;
    o.y = wv.y * (dy * inv) + bv.y;
    o.z = wv.z * (dz * inv) + bv.z;
    o.w = wv.w * (dw * inv) + bv.w;
    ((float4*)(Y + (size_t)row * D_))[tid] = o;
}

// ---------------- tf32 tensor-core GEMM: 128x128x16 tile, 8 warps ----------------
template<int EPI>  // 0: +bias  1: gelu(+bias)  2: +bias+residual
__global__ __launch_bounds__(256)
void tgemm_kernel(const float* __restrict__ A, const float* __restrict__ W,
                  const float* __restrict__ bias, const float* __restrict__ R,
                  float* __restrict__ C, int M, int N, int K) {
    __shared__ float As[2][128][20];
    __shared__ float Bs[2][16][136];

    int tid = threadIdx.x, lane = tid & 31, wid = tid >> 5;
    int wm = wid >> 1, wn = wid & 1;
    int row0 = blockIdx.y * 128, col0 = blockIdx.x * 128;
    int g = lane >> 2, tq = lane & 3;

    float acc[2][8][4];
    #pragma unroll
    for (int mi = 0; mi < 2; mi++)
        #pragma unroll
        for (int ni = 0; ni < 8; ni++)
            #pragma unroll
            for (int r = 0; r < 4; r++) acc[mi][ni][r] = 0.f;

    auto prefetch = [&](int st, int k0) {
        #pragma unroll
        for (int i = 0; i < 2; i++) {
            int c = tid + 256 * i;
            int ar = c >> 2, ac = (c & 3) << 2;
            cp_async16(smem_u32(&As[st][ar][ac]),
                       A + (size_t)(row0 + ar) * K + k0 + ac);
            int br = c >> 5, bc = (c & 31) << 2;
            cp_async16(smem_u32(&Bs[st][br][bc]),
                       W + (size_t)(k0 + br) * N + col0 + bc);
        }
        cp_commit();
    };

    int NK = K >> 4;
    prefetch(0, 0);
    for (int kt = 0; kt < NK; kt++) {
        int st = kt & 1;
        if (kt + 1 < NK) {
            prefetch(st ^ 1, (kt + 1) << 4);
            cp_wait<1>();
        } else {
            cp_wait<0>();
        }
        __syncthreads();

        #pragma unroll
        for (int kk = 0; kk < 16; kk += 8) {
            uint32_t af[2][4], bf[8][2];
            #pragma unroll
            for (int mi = 0; mi < 2; mi++) {
                int mb = wm * 32 + mi * 16;
                af[mi][0] = f2tf(As[st][mb + g][kk + tq]);
                af[mi][1] = f2tf(As[st][mb + g + 8][kk + tq]);
                af[mi][2] = f2tf(As[st][mb + g][kk + tq + 4]);
                af[mi][3] = f2tf(As[st][mb + g + 8][kk + tq + 4]);
            }
            #pragma unroll
            for (int ni = 0; ni < 8; ni++) {
                int nb = wn * 64 + ni * 8;
                bf[ni][0] = f2tf(Bs[st][kk + tq][nb + g]);
                bf[ni][1] = f2tf(Bs[st][kk + tq + 4][nb + g]);
            }
            #pragma unroll
            for (int mi = 0; mi < 2; mi++)
                #pragma unroll
                for (int ni = 0; ni < 8; ni++)
                    mma_tf32(acc[mi][ni], af[mi], bf[ni]);
        }
        __syncthreads();
    }

    #pragma unroll
    for (int mi = 0; mi < 2; mi++) {
        int rA = row0 + wm * 32 + mi * 16 + g;
        int rB = rA + 8;
        #pragma unroll
        for (int ni = 0; ni < 8; ni++) {
            int cg = col0 + wn * 64 + ni * 8 + 2 * tq;
            float b0 = bias[cg], b1 = bias[cg + 1];
            float v0 = acc[mi][ni][0] + b0;
            float v1 = acc[mi][ni][1] + b1;
            float v2 = acc[mi][ni][2] + b0;
            float v3 = acc[mi][ni][3] + b1;
            if (EPI == 1) {
                v0 = gelu_f(v0); v1 = gelu_f(v1);
                v2 = gelu_f(v2); v3 = gelu_f(v3);
            }
            if (EPI == 2) {
                v0 += R[(size_t)rA * N + cg];
                v1 += R[(size_t)rA * N + cg + 1];
                v2 += R[(size_t)rB * N + cg];
                v3 += R[(size_t)rB * N + cg + 1];
            }
            *(float2*)&C[(size_t)rA * N + cg] = make_float2(v0, v1);
            *(float2*)&C[(size_t)rB * N + cg] = make_float2(v2, v3);
        }
    }
}

// ---------------- KV assembly ----------------
__global__ void copy_past_k(const float* __restrict__ kin) {
    int idx = blockIdx.x * blockDim.x + threadIdx.x;
    int e = idx * 4;
    int bhd = e >> 10;
    int t   = e & 1023;
    *(float4*)&g_Kall[(size_t)bhd * T_ + t] = *(const float4*)&kin[e];
}

__global__ void copy_past_v(const float* __restrict__ vin) {
    int idx = blockIdx.x * blockDim.x + threadIdx.x;
    int e = idx * 4;
    int bh  = e >> 16;
    int rem = e & 65535;
    *(float4*)&g_Vall[(size_t)bh * T_ * DH_ + rem] = *(const float4*)&vin[e];
}

__global__ void scatter_kv(const float* __restrict__ qkv,
                           float* __restrict__ outk, float* __restrict__ outv) {
    int idx = blockIdx.x * blockDim.x + threadIdx.x;
    int bs = idx >> 10;
    int hd = idx & 1023;
    int b = bs >> 10, s = bs & 1023;
    int h = hd >> 6,  d = hd & 63;
    float kkv = qkv[(size_t)bs * D3_ + D_     + hd];
    float vvv = qkv[(size_t)bs * D3_ + 2 * D_ + hd];
    size_t kpos = (size_t)(b * H_ + h) * DH_ + d;
    g_Kall[kpos * T_ + P_ + s] = kkv;
    outk[kpos * S_ + s] = kkv;
    size_t vrow = (size_t)(b * H_ + h) * T_ + P_ + s;
    g_Vall[vrow * DH_ + d] = vvv;
    outv[((size_t)(b * H_ + h) * S_ + s) * DH_ + d] = vvv;
}

// ---------------- flash attention, tf32 MMA (Br=64, Bc=64, 4 warps) ----------------
__global__ __launch_bounds__(128)
void attn_mma_kernel(const float* __restrict__ qkv, float* __restrict__ Ab) {
    extern __shared__ uint32_t smu[];
    uint32_t (*Qs)[72] = (uint32_t(*)[72])smu;              // Q[i][d] (tf32)
    uint32_t (*Ks)[72] = (uint32_t(*)[72])(smu + 64 * 72);  // K^T[d][j] (tf32)
    uint32_t (*Vs)[72] = (uint32_t(*)[72])(smu + 2 * 64 * 72); // V[j][d] (tf32)

    int bh = blockIdx.x, b = bh >> 4, h = bh & 15;
    int s0 = blockIdx.y * 64;
    int tid = threadIdx.x, lane = tid & 31, wid = tid >> 5;
    int g = lane >> 2, tq = lane & 3;
    int mb = wid * 16;

    for (int it = tid; it < 1024; it += 128) {
        int r = it >> 4, c = (it & 15) << 2;
        float4 v = *(const float4*)&qkv[(size_t)(b * S_ + s0 + r) * D3_ + h * DH_ + c];
        Qs[r][c + 0] = f2tf(v.x); Qs[r][c + 1] = f2tf(v.y);
        Qs[r][c + 2] = f2tf(v.z); Qs[r][c + 3] = f2tf(v.w);
    }
    const float* Kb = g_Kall + (size_t)bh * DH_ * T_;
    const float* Vb = g_Vall + (size_t)bh * T_ * DH_;

    float m0 = -INFINITY, m1 = -INFINITY, l0 = 0.f, l1 = 0.f;
    float O[8][4];
    #pragma unroll
    for (int nd = 0; nd < 8; nd++)
        #pragma unroll
        for (int r = 0; r < 4; r++) O[nd][r] = 0.f;

    for (int t0 = 0; t0 < T_; t0 += 64) {
        __syncthreads();
        for (int it = tid; it < 1024; it += 128) {
            int r = it >> 4, c = (it & 15) << 2;
            float4 kv = *(const float4*)&Kb[(size_t)r * T_ + t0 + c];
            Ks[r][c + 0] = f2tf(kv.x); Ks[r][c + 1] = f2tf(kv.y);
            Ks[r][c + 2] = f2tf(kv.z); Ks[r][c + 3] = f2tf(kv.w);
            float4 vv = *(const float4*)&Vb[(size_t)(t0 + r) * DH_ + c];
            Vs[r][c + 0] = f2tf(vv.x); Vs[r][c + 1] = f2tf(vv.y);
            Vs[r][c + 2] = f2tf(vv.z); Vs[r][c + 3] = f2tf(vv.w);
        }
        __syncthreads();

        // S = Q K^T  (16 rows per warp x 64 keys)
        float sv[8][4];
        #pragma unroll
        for (int ni = 0; ni < 8; ni++)
            #pragma unroll
            for (int r = 0; r < 4; r++) sv[ni][r] = 0.f;

        #pragma unroll
        for (int kk = 0; kk < 64; kk += 8) {
            uint32_t af[4];
            af[0] = Qs[mb + g][kk + tq];
            af[1] = Qs[mb + g + 8][kk + tq];
            af[2] = Qs[mb + g][kk + tq + 4];
            af[3] = Qs[mb + g + 8][kk + tq + 4];
            #pragma unroll
            for (int ni = 0; ni < 8; ni++) {
                uint32_t bf[2] = { Ks[kk + tq][ni * 8 + g], Ks[kk + tq + 4][ni * 8 + g] };
                mma_tf32(sv[ni], af, bf);
            }
        }

        // online softmax (rows g and g+8 of this warp's 16-row block)
        float mx0 = -INFINITY, mx1 = -INFINITY;
        #pragma unroll
        for (int ni = 0; ni < 8; ni++) {
            mx0 = fmaxf(mx0, fmaxf(sv[ni][0], sv[ni][1]));
            mx1 = fmaxf(mx1, fmaxf(sv[ni][2], sv[ni][3]));
        }
        mx0 = fmaxf(mx0, __shfl_xor_sync(0xffffffffu, mx0, 1));
        mx0 = fmaxf(mx0, __shfl_xor_sync(0xffffffffu, mx0, 2));
        mx1 = fmaxf(mx1, __shfl_xor_sync(0xffffffffu, mx1, 1));
        mx1 = fmaxf(mx1, __shfl_xor_sync(0xffffffffu, mx1, 2));
        float mn0 = fmaxf(m0, mx0), mn1 = fmaxf(m1, mx1);
        float sc0 = __expf(m0 - mn0), sc1 = __expf(m1 - mn1);
        float ps0 = 0.f, ps1 = 0.f;
        #pragma unroll
        for (int ni = 0; ni < 8; ni++) {
            sv[ni][0] = __expf(sv[ni][0] - mn0);
            sv[ni][1] = __expf(sv[ni][1] - mn0);
            sv[ni][2] = __expf(sv[ni][2] - mn1);
            sv[ni][3] = __expf(sv[ni][3] - mn1);
            ps0 += sv[ni][0] + sv[ni][1];
            ps1 += sv[ni][2] + sv[ni][3];
        }
        ps0 += __shfl_xor_sync(0xffffffffu, ps0, 1);
        ps0 += __shfl_xor_sync(0xffffffffu, ps0, 2);
        ps1 += __shfl_xor_sync(0xffffffffu, ps1, 1);
        ps1 += __shfl_xor_sync(0xffffffffu, ps1, 2);
        l0 = l0 * sc0 + ps0;
        l1 = l1 * sc1 + ps1;
        m0 = mn0; m1 = mn1;
        #pragma unroll
        for (int nd = 0; nd < 8; nd++) {
            O[nd][0] *= sc0; O[nd][1] *= sc0;
            O[nd][2] *= sc1; O[nd][3] *= sc1;
        }

        // O += P V : relayout C-frag P -> A-frag via intra-quad shuffles
        #pragma unroll
        for (int ni = 0; ni < 8; ni++) {
            int sl0 = (g << 2) + (tq >> 1);
            int sl1 = sl0 + 2;
            float v00 = __shfl_sync(0xffffffffu, sv[ni][0], sl0);
            float v01 = __shfl_sync(0xffffffffu, sv[ni][1], sl0);
            float v10 = __shfl_sync(0xffffffffu, sv[ni][0], sl1);
            float v11 = __shfl_sync(0xffffffffu, sv[ni][1], sl1);
            float w00 = __shfl_sync(0xffffffffu, sv[ni][2], sl0);
            float w01 = __shfl_sync(0xffffffffu, sv[ni][3], sl0);
            float w10 = __shfl_sync(0xffffffffu, sv[ni][2], sl1);
            float w11 = __shfl_sync(0xffffffffu, sv[ni][3], sl1);
            bool odd = (tq & 1);
            uint32_t af[4];
            af[0] = f2tf(odd ? v01 : v00);   // P[g   ][ni*8+tq]
            af[1] = f2tf(odd ? w01 : w00);   // P[g+8 ][ni*8+tq]
            af[2] = f2tf(odd ? v11 : v10);   // P[g   ][ni*8+tq+4]
            af[3] = f2tf(odd ? w11 : w10);   // P[g+8 ][ni*8+tq+4]
            #pragma unroll
            for (int nd = 0; nd < 8; nd++) {
                uint32_t bf[2] = { Vs[ni * 8 + tq][nd * 8 + g], Vs[ni * 8 + tq + 4][nd * 8 + g] };
                mma_tf32(O[nd], af, bf);
            }
        }
    }

    float inv0 = 1.0f / l0, inv1 = 1.0f / l1;
    int rA = s0 + mb + g, rB = rA + 8;
    #pragma unroll
    for (int nd = 0; nd < 8; nd++) {
        int col = h * DH_ + nd * 8 + 2 * tq;
        *(float2*)&Ab[(size_t)(b * S_ + rA) * D_ + col] =
            make_float2(O[nd][0] * inv0, O[nd][1] * inv0);
        *(float2*)&Ab[(size_t)(b * S_ + rB) * D_ + col] =
            make_float2(O[nd][2] * inv1, O[nd][3] * inv1);
    }
}

// ---------------- launch ----------------
extern "C" void kernel_launch(void* const* d_in, const int* in_sizes, int n_in,
                              void* d_out, int out_size) {
    const float* x      = (const float*)d_in[0];
    const float* kin    = (const float*)d_in[1];
    const float* vin    = (const float*)d_in[2];
    const float* ln1w   = (const float*)d_in[3];
    const float* ln1b   = (const float*)d_in[4];
    const float* ln2w   = (const float*)d_in[5];
    const float* ln2b   = (const float*)d_in[6];
    const float* w_attn = (const float*)d_in[7];
    const float* b_attn = (const float*)d_in[8];
    const float* w_proj = (const float*)d_in[9];
    const float* b_proj = (const float*)d_in[10];
    const float* w_fc   = (const float*)d_in[11];
    const float* b_fc   = (const float*)d_in[12];
    const float* w_fc2  = (const float*)d_in[13];
    const float* b_fc2  = (const float*)d_in[14];

    float* out_x = (float*)d_out;
    float* out_k = out_x + (size_t)NT_ * D_;
    float* out_v = out_k + (size_t)NT_ * D_;

    float *ph, *pqkv, *pa, *px1, *ph2, *pm;
    cudaGetSymbolAddress((void**)&ph,   g_h);
    cudaGetSymbolAddress((void**)&pqkv, g_qkv);
    cudaGetSymbolAddress((void**)&pa,   g_a);
    cudaGetSymbolAddress((void**)&px1,  g_x1);
    cudaGetSymbolAddress((void**)&ph2,  g_h2);
    cudaGetSymbolAddress((void**)&pm,   g_m);

    // 1. ln1
    ln_kernel<<<NT_, 256>>>(x, ln1w, ln1b, ph);
    // 2. qkv gemm (tf32 MMA)
    tgemm_kernel<0><<<dim3(D3_ / 128, NT_ / 128), 256>>>(ph, w_attn, b_attn, nullptr,
                                                         pqkv, NT_, D3_, D_);
    // 3. assemble KV cache (+ write new_k/new_v outputs)
    copy_past_k<<<2048, 256>>>(kin);
    copy_past_v<<<2048, 256>>>(vin);
    scatter_kv<<<8192, 256>>>(pqkv, out_k, out_v);
    // 4. attention (tf32 MMA)
    int attn_smem = 3 * 64 * 72 * (int)sizeof(uint32_t);  // 55296
    cudaFuncSetAttribute(attn_mma_kernel, cudaFuncAttributeMaxDynamicSharedMemorySize, attn_smem);
    attn_mma_kernel<<<dim3(B_ * H_, S_ / 64), 128, attn_smem>>>(pqkv, pa);
    // 5. proj + residual
    tgemm_kernel<2><<<dim3(D_ / 128, NT_ / 128), 256>>>(pa, w_proj, b_proj, x,
                                                        px1, NT_, D_, D_);
    // 6. ln2
    ln_kernel<<<NT_, 256>>>(px1, ln2w, ln2b, ph2);
    // 7. fc + gelu
    tgemm_kernel<1><<<dim3(D4_ / 128, NT_ / 128), 256>>>(ph2, w_fc, b_fc, nullptr,
                                                         pm, NT_, D4_, D_);
    // 8. fc2 + residual -> out x
    tgemm_kernel<2><<<dim3(D_ / 128, NT_ / 128), 256>>>(pm, w_fc2, b_fc2, px1,
                                                        out_x, NT_, D_, D4_);
}